// round 4
// baseline (speedup 1.0000x reference)
#include <cuda_runtime.h>
#include <cstddef>

#define Bx 16
#define Lx 4096
#define Dx 1024
#define NSPLIT 32
#define ROWS_PER_SPLIT (Lx / NSPLIT)   // 128
#define SBLK 32                        // rows per score block
#define NSBLK (Lx / SBLK)              // 128 score blocks per batch

// ---- scratch (__device__ globals; no allocation allowed) ----
__device__ float g_df[Bx * Dx];                // dec_feature
__device__ float g_score[Bx * Lx];             // pre-softmax scores
__device__ float g_partial[Bx * NSPLIT * Dx];  // context partials
__device__ int   g_ctr_s[Bx];                  // score-block arrival counters
__device__ int   g_ctr_c[Bx];                  // context-block arrival counters

// d_out layout (float32): attn, context, new_coverage
#define ATTN_OFF 0
#define CTX_OFF  (Bx * Lx)
#define COV_OFF  (Bx * Lx + Bx * Dx)

__device__ __forceinline__ float tanh_approx(float x) {
    float y;
    asm("tanh.approx.f32 %0, %1;" : "=f"(y) : "f"(x));
    return y;
}

// ============================================================
// Kernel 1: dec_feature[b,d] = sum_k dec_hidden[b,k]*W_feat[d,k] + b_feat[d]
// ============================================================
__global__ void k_decfeat(const float* __restrict__ dh,
                          const float* __restrict__ W,
                          const float* __restrict__ bias) {
    int d = blockIdx.x;
    int t = threadIdx.x;               // 0..255
    float4 w4 = ((const float4*)(W + (size_t)d * Dx))[t];

    float acc[Bx];
#pragma unroll
    for (int b = 0; b < Bx; b++) {
        float4 h4 = ((const float4*)(dh + (size_t)b * Dx))[t];
        acc[b] = w4.x * h4.x + w4.y * h4.y + w4.z * h4.z + w4.w * h4.w;
    }
#pragma unroll
    for (int b = 0; b < Bx; b++) {
#pragma unroll
        for (int off = 16; off; off >>= 1)
            acc[b] += __shfl_down_sync(0xffffffffu, acc[b], off);
    }
    __shared__ float s[8][Bx];
    int warp = t >> 5, lane = t & 31;
    if (lane == 0) {
#pragma unroll
        for (int b = 0; b < Bx; b++) s[warp][b] = acc[b];
    }
    __syncthreads();
    if (t < Bx) {
        float v = 0.f;
#pragma unroll
        for (int w = 0; w < 8; w++) v += s[w][t];
        g_df[t * Dx + d] = v + bias[d];
    }
}

// ============================================================
// Kernel 2: score + fused masked softmax (last block per b).
// Weights register-resident: NO smem traffic in the hot loop.
// Warp w: half h=w&1 of the D-row, row group g=w>>1; 8 rows per warp.
// ============================================================
__global__ void __launch_bounds__(256, 2)
k_score(const float* __restrict__ ef,
        const float* __restrict__ cov,
        const float* __restrict__ wscore,
        const float* __restrict__ wcov,
        const float* __restrict__ mask,
        float* __restrict__ out) {
    int b  = blockIdx.y;
    int l0 = blockIdx.x * SBLK;
    int t = threadIdx.x, w = t >> 5, lane = t & 31;
    int h = w & 1, g = w >> 1;

    __shared__ float s_part[SBLK][2];
    __shared__ float s_cov[SBLK];
    __shared__ float s_red[8];
    __shared__ int   s_last;

    if (t < SBLK) s_cov[t] = cov[b * Lx + l0 + t];

    const float4* dfp = (const float4*)(g_df + (size_t)b * Dx);
    const float4* wsp = (const float4*)wscore;
    const float4* wcp = (const float4*)wcov;

    float4 df4[4], ws4[4], wc4[4];
#pragma unroll
    for (int j = 0; j < 4; j++) {
        int slot = h * 128 + j * 32 + lane;  // float4 slot in row (0..255)
        df4[j] = dfp[slot];
        ws4[j] = wsp[slot];
        wc4[j] = wcp[slot];
    }
    __syncthreads();

#pragma unroll 2
    for (int i = 0; i < 8; i++) {
        int rloc = g + 4 * i;
        float c = s_cov[rloc];
        const float4* row = (const float4*)(ef + ((size_t)(b * Lx + l0 + rloc)) * Dx);
        float acc = 0.f;
#pragma unroll
        for (int j = 0; j < 4; j++) {
            float4 e = __ldcs(&row[h * 128 + j * 32 + lane]);
            acc += tanh_approx(fmaf(c, wc4[j].x, e.x + df4[j].x)) * ws4[j].x
                 + tanh_approx(fmaf(c, wc4[j].y, e.y + df4[j].y)) * ws4[j].y
                 + tanh_approx(fmaf(c, wc4[j].z, e.z + df4[j].z)) * ws4[j].z
                 + tanh_approx(fmaf(c, wc4[j].w, e.w + df4[j].w)) * ws4[j].w;
        }
#pragma unroll
        for (int off = 16; off; off >>= 1)
            acc += __shfl_down_sync(0xffffffffu, acc, off);
        if (lane == 0) s_part[rloc][h] = acc;
    }
    __syncthreads();
    if (t < SBLK)
        g_score[b * Lx + l0 + t] = s_part[t][0] + s_part[t][1];

    // ---- arrival protocol: stores -> bar (cta release) -> fence(gpu) -> atomic
    __syncthreads();
    if (t == 0) {
        __threadfence();
        int old = atomicAdd(&g_ctr_s[b], 1);
        s_last = (old == NSBLK - 1);
        if (s_last) g_ctr_s[b] = 0;   // reset for next graph replay
    }
    __syncthreads();
    if (!s_last) return;
    __threadfence();

    // ---- last block per b: masked softmax over the full row ----
    const float4* sc = (const float4*)(g_score + (size_t)b * Lx);
    float4 v[4];
#pragma unroll
    for (int k = 0; k < 4; k++) v[k] = sc[t + k * 256];

    // block max
    float mx = -1e30f;
#pragma unroll
    for (int k = 0; k < 4; k++)
        mx = fmaxf(mx, fmaxf(fmaxf(v[k].x, v[k].y), fmaxf(v[k].z, v[k].w)));
#pragma unroll
    for (int off = 16; off; off >>= 1)
        mx = fmaxf(mx, __shfl_xor_sync(0xffffffffu, mx, off));
    if (lane == 0) s_red[w] = mx;
    __syncthreads();
#pragma unroll
    for (int k = 0; k < 8; k++) mx = fmaxf(mx, s_red[k]);
    __syncthreads();

    // e * mask, block sum  (softmax -> *mask -> /sum collapses to em/sum(em))
    const float4* mkp = (const float4*)(mask + (size_t)b * Lx);
    float4 em[4];
    float lsum = 0.f;
#pragma unroll
    for (int k = 0; k < 4; k++) {
        float4 m4 = mkp[t + k * 256];
        em[k].x = expf(v[k].x - mx) * m4.x;
        em[k].y = expf(v[k].y - mx) * m4.y;
        em[k].z = expf(v[k].z - mx) * m4.z;
        em[k].w = expf(v[k].w - mx) * m4.w;
        lsum += em[k].x + em[k].y + em[k].z + em[k].w;
    }
#pragma unroll
    for (int off = 16; off; off >>= 1)
        lsum += __shfl_xor_sync(0xffffffffu, lsum, off);
    if (lane == 0) s_red[w] = lsum;
    __syncthreads();
    float tot = 0.f;
#pragma unroll
    for (int k = 0; k < 8; k++) tot += s_red[k];
    float inv = 1.f / tot;

    const float4* cvp = (const float4*)(cov + (size_t)b * Lx);
    float4* attnp = (float4*)(out + ATTN_OFF + (size_t)b * Lx);
    float4* covp  = (float4*)(out + COV_OFF  + (size_t)b * Lx);
#pragma unroll
    for (int k = 0; k < 4; k++) {
        float4 c4 = cvp[t + k * 256];
        float4 a4;
        a4.x = em[k].x * inv; a4.y = em[k].y * inv;
        a4.z = em[k].z * inv; a4.w = em[k].w * inv;
        attnp[t + k * 256] = a4;
        float4 n4;
        n4.x = a4.x + c4.x; n4.y = a4.y + c4.y;
        n4.z = a4.z + c4.z; n4.w = a4.w + c4.w;
        covp[t + k * 256] = n4;
    }
}

// ============================================================
// Kernel 3: context partials + fused deterministic reduce
// (last block per b sums all NSPLIT partials in fixed order).
// ============================================================
__global__ void __launch_bounds__(256)
k_context(const float* __restrict__ eo,
          const float* __restrict__ attn,
          float* __restrict__ out) {
    int b  = blockIdx.y;
    int sp = blockIdx.x;     // 0..NSPLIT-1
    int t  = threadIdx.x;    // 0..255
    int l0 = sp * ROWS_PER_SPLIT;

    __shared__ float sa[ROWS_PER_SPLIT];
    __shared__ int s_last;
    if (t < ROWS_PER_SPLIT) sa[t] = attn[b * Lx + l0 + t];
    __syncthreads();

    const float4* base = (const float4*)eo + ((size_t)(b * Lx + l0)) * (Dx / 4) + t;
    float4 acc = make_float4(0.f, 0.f, 0.f, 0.f);
#pragma unroll 2
    for (int i = 0; i < ROWS_PER_SPLIT; i += 4) {
        float4 v0 = __ldcs(base + (size_t)(i + 0) * (Dx / 4));
        float4 v1 = __ldcs(base + (size_t)(i + 1) * (Dx / 4));
        float4 v2 = __ldcs(base + (size_t)(i + 2) * (Dx / 4));
        float4 v3 = __ldcs(base + (size_t)(i + 3) * (Dx / 4));
        float a0 = sa[i], a1 = sa[i + 1], a2 = sa[i + 2], a3 = sa[i + 3];
        acc.x = fmaf(a0, v0.x, acc.x); acc.y = fmaf(a0, v0.y, acc.y);
        acc.z = fmaf(a0, v0.z, acc.z); acc.w = fmaf(a0, v0.w, acc.w);
        acc.x = fmaf(a1, v1.x, acc.x); acc.y = fmaf(a1, v1.y, acc.y);
        acc.z = fmaf(a1, v1.z, acc.z); acc.w = fmaf(a1, v1.w, acc.w);
        acc.x = fmaf(a2, v2.x, acc.x); acc.y = fmaf(a2, v2.y, acc.y);
        acc.z = fmaf(a2, v2.z, acc.z); acc.w = fmaf(a2, v2.w, acc.w);
        acc.x = fmaf(a3, v3.x, acc.x); acc.y = fmaf(a3, v3.y, acc.y);
        acc.z = fmaf(a3, v3.z, acc.z); acc.w = fmaf(a3, v3.w, acc.w);
    }
    ((float4*)(g_partial + ((size_t)(b * NSPLIT + sp)) * Dx))[t] = acc;

    // ---- arrival protocol: stores -> bar (cta release) -> fence(gpu) -> atomic
    __syncthreads();              // ensure ALL warps' partial stores precede signal
    if (t == 0) {
        __threadfence();
        int old = atomicAdd(&g_ctr_c[b], 1);
        s_last = (old == NSPLIT - 1);
        if (s_last) g_ctr_c[b] = 0;   // reset for next graph replay
    }
    __syncthreads();
    if (!s_last) return;
    __threadfence();

    float4 sum = make_float4(0.f, 0.f, 0.f, 0.f);
#pragma unroll
    for (int s = 0; s < NSPLIT; s++) {
        float4 p = ((const float4*)(g_partial + ((size_t)(b * NSPLIT + s)) * Dx))[t];
        sum.x += p.x; sum.y += p.y; sum.z += p.z; sum.w += p.w;
    }
    ((float4*)(out + CTX_OFF + (size_t)b * Dx))[t] = sum;
}

// ============================================================
extern "C" void kernel_launch(void* const* d_in, const int* in_sizes, int n_in,
                              void* d_out, int out_size) {
    const float* dec_hidden  = (const float*)d_in[0];
    const float* enc_output  = (const float*)d_in[1];
    const float* enc_feature = (const float*)d_in[2];
    const float* enc_mask    = (const float*)d_in[3];
    // d_in[4] = sec_attn : dead code in reference
    const float* coverage    = (const float*)d_in[5];
    const float* W_feat      = (const float*)d_in[6];
    const float* b_feat      = (const float*)d_in[7];
    const float* w_score     = (const float*)d_in[8];
    const float* w_cov       = (const float*)d_in[9];
    float* out = (float*)d_out;

    k_decfeat<<<Dx, 256>>>(dec_hidden, W_feat, b_feat);
    k_score  <<<dim3(NSBLK, Bx), 256>>>(enc_feature, coverage, w_score, w_cov,
                                        enc_mask, out);
    k_context<<<dim3(NSPLIT, Bx), 256>>>(enc_output, out + ATTN_OFF, out);
}